// round 8
// baseline (speedup 1.0000x reference)
#include <cuda_runtime.h>
#include <cuda_fp16.h>
#include <cuda_bf16.h>

// RoIAlign: features [4,1024,64,64] f32, rois [2048,5] f32 -> out [2048,1024,7,7] f32
//
// Persistent kernel: 304 blocks (2/SM), each grabs (batch, 8-ch chunk) tiles
// from a global atomic counter (512 tiles), stages the tile's features into
// smem as fp16 channel-interleaved uint4 (8 ch/site, row stride 65), then
// processes that batch's (roi,bin) entry table with a software-pipelined
// geom prefetch. Per entry: 1 LDG.64 (prefetched), 4 LDS.128, 8 STG.32
// (coalesced 128B warp runs). Geometry packed to 8 B/entry by a prekernel.

#define B_    4
#define C_    1024
#define H_    64
#define W_    64
#define N_    2048
#define BINS  49
#define SCALE 0.0625f

#define CH       8
#define PLANE4   65                         // uint4-site row stride
#define SMEM_BYTES (H_ * PLANE4 * 16)       // 66560 B
#define NTHREADS 1024
#define NTILES   ((C_ / CH) * B_)           // 512
#define NBLOCKS  304                        // 2 per SM on 152-SM GB300

__device__ int   g_roi_list[B_][N_];
__device__ int   g_roi_cnt[B_];
__device__ int   g_tile_ctr;
__device__ uint2 g_geom[B_][N_ * BINS];

__global__ void zero_cnt_kernel() {
    if (threadIdx.x < B_) g_roi_cnt[threadIdx.x] = 0;
    if (threadIdx.x == 0) g_tile_ctr = 0;
}

__global__ void build_list_kernel(const float* __restrict__ rois) {
    int n = blockIdx.x * blockDim.x + threadIdx.x;
    if (n < N_) {
        int b = (int)rois[n * 5];
        int pos = atomicAdd(&g_roi_cnt[b], 1);
        g_roi_list[b][pos] = n;
    }
}

__global__ void geom_kernel(const float* __restrict__ rois) {
    int idx = blockIdx.x * 256 + threadIdx.x;      // 0 .. N_*BINS-1
    int b = blockIdx.y;
    if (idx >= N_ * BINS) return;
    int slot = idx / BINS;
    int bin  = idx - slot * BINS;
    if (slot >= g_roi_cnt[b]) return;
    int n = g_roi_list[b][slot];

    const float* rp = rois + n * 5;
    float x1 = rp[1] * SCALE;
    float y1 = rp[2] * SCALE;
    float x2 = rp[3] * SCALE;
    float y2 = rp[4] * SCALE;
    float bw = fmaxf(x2 - x1, 0.0f) * (1.0f / 6.0f);
    float bh = fmaxf(y2 - y1, 0.0f) * (1.0f / 6.0f);
    float phf = (float)(bin / 7);
    float pwf = (float)(bin % 7);
    float h = y1 + phf * bh;
    float w = x1 + pwf * bw;

    float hstart = fminf(floorf(h), (float)(H_ - 2));
    float wstart = fminf(floorf(w), (float)(W_ - 2));
    float hr = h - hstart;
    float wr = w - wstart;
    bool valid = (h >= 0.0f) && (h < (float)H_) &&
                 (w >= 0.0f) && (w < (float)W_);
    int hs = min(max((int)hstart, 0), H_ - 2);
    int ws = min(max((int)wstart, 0), W_ - 2);

    unsigned hrq = min((int)(hr * 32768.0f + 0.5f), 65535);
    unsigned wrq = min((int)(wr * 32768.0f + 0.5f), 65535);

    unsigned a = (unsigned)bin | ((unsigned)n << 6) |
                 ((unsigned)ws << 17) | ((unsigned)hs << 23);
    if (!valid) a |= 0x80000000u;

    g_geom[b][idx] = make_uint2(a, (hrq << 16) | wrq);
}

__global__ __launch_bounds__(NTHREADS, 2)
void roialign_kernel(const float* __restrict__ features,
                     float* __restrict__ out) {
    extern __shared__ uint4 sm[];                 // [hs*65+ws] -> 8 fp16 ch
    __shared__ int s_tile;

    const int lane = threadIdx.x & 31;
    const int warp = threadIdx.x >> 5;            // 0..31

    for (;;) {
        if (threadIdx.x == 0) s_tile = atomicAdd(&g_tile_ctr, 1);
        __syncthreads();                          // also: prev tile fully done
        const int tile = s_tile;
        if (tile >= NTILES) return;

        const int b  = tile & (B_ - 1);
        const int c0 = (tile >> 2) * CH;

        // ---- Stage: 8 coalesced channel streams -> fp16 interleaved ----
        {
            const float* src = features + (size_t)(b * C_ + c0) * (H_ * W_);
            #pragma unroll
            for (int k = 0; k < (H_ * W_) / NTHREADS; k++) {
                int i = k * NTHREADS + threadIdx.x;
                int row = i >> 6;
                int col = i & 63;
                __half2 h01 = __floats2half2_rn(src[i],            src[1 * 4096 + i]);
                __half2 h23 = __floats2half2_rn(src[2 * 4096 + i], src[3 * 4096 + i]);
                __half2 h45 = __floats2half2_rn(src[4 * 4096 + i], src[5 * 4096 + i]);
                __half2 h67 = __floats2half2_rn(src[6 * 4096 + i], src[7 * 4096 + i]);
                uint4 v;
                v.x = *reinterpret_cast<unsigned*>(&h01);
                v.y = *reinterpret_cast<unsigned*>(&h23);
                v.z = *reinterpret_cast<unsigned*>(&h45);
                v.w = *reinterpret_cast<unsigned*>(&h67);
                sm[row * PLANE4 + col] = v;
            }
        }
        __syncthreads();

        const int E = g_roi_cnt[b] * BINS;
        const uint2* __restrict__ gt = g_geom[b];
        float* __restrict__ obase = out + (size_t)c0 * BINS;

        // software-pipelined geom prefetch
        int entry0 = warp * 32 + lane;
        uint2 gnext = (entry0 < E) ? __ldg(&gt[entry0]) : make_uint2(0u, 0u);

        for (int base = warp * 32; base < E; base += NTHREADS) {
            uint2 g = gnext;
            int nx = base + NTHREADS + lane;
            if (nx < E) gnext = __ldg(&gt[nx]);

            if (base + lane < E) {
                unsigned a = g.x;
                int bin = a & 63;
                int n   = (a >> 6) & 2047;
                int ws  = (a >> 17) & 63;
                int hs  = (a >> 23) & 63;
                float hr = (float)(g.y >> 16)    * (1.0f / 32768.0f);
                float wr = (float)(g.y & 0xFFFF) * (1.0f / 32768.0f);

                float omh = 1.0f - hr, omw = 1.0f - wr;
                float wa = omh * omw;
                float wb = omh * wr;
                float wc = hr * omw;
                float wd = hr * wr;
                if ((int)a < 0) { wa = wb = wc = wd = 0.0f; }

                int s = hs * PLANE4 + ws;
                uint4 ul = sm[s];
                uint4 ur = sm[s + 1];
                uint4 dl = sm[s + PLANE4];
                uint4 dr = sm[s + PLANE4 + 1];

                float* o = obase + (size_t)n * (C_ * BINS) + bin;

                const unsigned* pul = &ul.x;
                const unsigned* pur = &ur.x;
                const unsigned* pdl = &dl.x;
                const unsigned* pdr = &dr.x;
                #pragma unroll
                for (int j = 0; j < 4; j++) {
                    float2 fu = __half22float2(*reinterpret_cast<const __half2*>(&pul[j]));
                    float2 fr = __half22float2(*reinterpret_cast<const __half2*>(&pur[j]));
                    float2 fd = __half22float2(*reinterpret_cast<const __half2*>(&pdl[j]));
                    float2 fb = __half22float2(*reinterpret_cast<const __half2*>(&pdr[j]));
                    o[(2 * j)     * BINS] = wa * fu.x + wb * fr.x + wc * fd.x + wd * fb.x;
                    o[(2 * j + 1) * BINS] = wa * fu.y + wb * fr.y + wc * fd.y + wd * fb.y;
                }
            }
        }
    }
}

extern "C" void kernel_launch(void* const* d_in, const int* in_sizes, int n_in,
                              void* d_out, int out_size) {
    const float* features = (const float*)d_in[0];
    const float* rois     = (const float*)d_in[1];
    float* out            = (float*)d_out;

    cudaFuncSetAttribute(roialign_kernel,
                         cudaFuncAttributeMaxDynamicSharedMemorySize,
                         SMEM_BYTES);

    zero_cnt_kernel<<<1, 32>>>();
    build_list_kernel<<<N_ / 256, 256>>>(rois);
    {
        dim3 g((N_ * BINS + 255) / 256, B_);
        geom_kernel<<<g, 256>>>(rois);
    }
    roialign_kernel<<<NBLOCKS, NTHREADS, SMEM_BYTES>>>(features, out);
}

// round 9
// speedup vs baseline: 1.2665x; 1.2665x over previous
#include <cuda_runtime.h>
#include <cuda_fp16.h>
#include <cuda_bf16.h>

// RoIAlign: features [4,1024,64,64] f32, rois [2048,5] f32 -> out [2048,1024,7,7] f32
//
// Geometry prekernel now precomputes EVERYTHING per (roi,bin): packed (hs,ws),
// output element offset, and the 4 bilinear weights as half2 pairs (zeroed if
// invalid). Main kernel: block = (batch, 8-ch chunk, entry-slice), 1024
// threads, 65KB fp16 channel-interleaved smem (2 CTAs/SM). Inner loop per
// entry (8 outputs): 1 LDG.128 (prefetched) + 4 LDS.128 + 4 weight splats +
// 16 HFMA2 + 8 F2F + 8 coalesced STG.32  (~50 instr vs ~103 before: the
// kernel was issue-bound on F2F conversions).

#define B_    4
#define C_    1024
#define H_    64
#define W_    64
#define N_    2048
#define BINS  49
#define SCALE 0.0625f

#define CH       8
#define PLANE4   65                         // uint4-site row stride
#define SMEM_BYTES (H_ * PLANE4 * 16)       // 66560 B
#define NTHREADS 1024
#define SLICES   2

__device__ int   g_roi_list[B_][N_];
__device__ int   g_roi_cnt[B_];
__device__ uint4 g_geom[B_][N_ * BINS];

__global__ void zero_cnt_kernel() {
    if (threadIdx.x < B_) g_roi_cnt[threadIdx.x] = 0;
}

__global__ void build_list_kernel(const float* __restrict__ rois) {
    int n = blockIdx.x * blockDim.x + threadIdx.x;
    if (n < N_) {
        int b = (int)rois[n * 5];
        int pos = atomicAdd(&g_roi_cnt[b], 1);
        g_roi_list[b][pos] = n;
    }
}

__global__ void geom_kernel(const float* __restrict__ rois) {
    int idx = blockIdx.x * 256 + threadIdx.x;      // 0 .. N_*BINS-1
    int b = blockIdx.y;
    if (idx >= N_ * BINS) return;
    int slot = idx / BINS;
    int bin  = idx - slot * BINS;
    if (slot >= g_roi_cnt[b]) return;
    int n = g_roi_list[b][slot];

    const float* rp = rois + n * 5;
    float x1 = rp[1] * SCALE;
    float y1 = rp[2] * SCALE;
    float x2 = rp[3] * SCALE;
    float y2 = rp[4] * SCALE;
    float bw = fmaxf(x2 - x1, 0.0f) * (1.0f / 6.0f);
    float bh = fmaxf(y2 - y1, 0.0f) * (1.0f / 6.0f);
    float phf = (float)(bin / 7);
    float pwf = (float)(bin % 7);
    float h = y1 + phf * bh;
    float w = x1 + pwf * bw;

    float hstart = fminf(floorf(h), (float)(H_ - 2));
    float wstart = fminf(floorf(w), (float)(W_ - 2));
    float hr = h - hstart;
    float wr = w - wstart;
    bool valid = (h >= 0.0f) && (h < (float)H_) &&
                 (w >= 0.0f) && (w < (float)W_);
    int hs = min(max((int)hstart, 0), H_ - 2);
    int ws = min(max((int)wstart, 0), W_ - 2);

    float omh = 1.0f - hr, omw = 1.0f - wr;
    float wa = omh * omw;
    float wb = omh * wr;
    float wc = hr * omw;
    float wd = hr * wr;
    if (!valid) { wa = wb = wc = wd = 0.0f; }

    __half2 hab = __floats2half2_rn(wa, wb);
    __half2 hcd = __floats2half2_rn(wc, wd);

    uint4 e;
    e.x = (unsigned)ws | ((unsigned)hs << 6);
    e.y = (unsigned)(n * (C_ * BINS) + bin);
    e.z = *reinterpret_cast<unsigned*>(&hab);
    e.w = *reinterpret_cast<unsigned*>(&hcd);
    g_geom[b][idx] = e;
}

__global__ __launch_bounds__(NTHREADS, 2)
void roialign_kernel(const float* __restrict__ features,
                     float* __restrict__ out) {
    extern __shared__ uint4 sm[];                 // [hs*65+ws] -> 8 fp16 ch

    const int b     = blockIdx.y;
    const int c0    = (blockIdx.x >> 1) * CH;
    const int slice = blockIdx.x & (SLICES - 1);

    // ---- Stage: 8 coalesced channel streams -> fp16 interleaved ----
    {
        const float* src = features + (size_t)(b * C_ + c0) * (H_ * W_);
        #pragma unroll
        for (int k = 0; k < (H_ * W_) / NTHREADS; k++) {
            int i = k * NTHREADS + threadIdx.x;
            int row = i >> 6;
            int col = i & 63;
            __half2 h01 = __floats2half2_rn(src[i],            src[1 * 4096 + i]);
            __half2 h23 = __floats2half2_rn(src[2 * 4096 + i], src[3 * 4096 + i]);
            __half2 h45 = __floats2half2_rn(src[4 * 4096 + i], src[5 * 4096 + i]);
            __half2 h67 = __floats2half2_rn(src[6 * 4096 + i], src[7 * 4096 + i]);
            uint4 v;
            v.x = *reinterpret_cast<unsigned*>(&h01);
            v.y = *reinterpret_cast<unsigned*>(&h23);
            v.z = *reinterpret_cast<unsigned*>(&h45);
            v.w = *reinterpret_cast<unsigned*>(&h67);
            sm[row * PLANE4 + col] = v;
        }
    }
    __syncthreads();

    const int E    = g_roi_cnt[b] * BINS;
    const int lane = threadIdx.x & 31;
    const int warp = threadIdx.x >> 5;            // 0..31

    const uint4* __restrict__ gt = g_geom[b];
    float* __restrict__ obase = out + (size_t)c0 * BINS;

    // chunk id = slice*32 + warp, stride SLICES*32 chunks of 32 entries
    int base0 = (slice * 32 + warp) * 32;
    uint4 gnext = (base0 + lane < E) ? __ldg(&gt[base0 + lane])
                                     : make_uint4(0u, 0u, 0u, 0u);

    for (int base = base0; base < E; base += SLICES * NTHREADS) {
        uint4 g = gnext;
        int nx = base + SLICES * NTHREADS + lane;
        if (nx < E) gnext = __ldg(&gt[nx]);

        if (base + lane < E) {
            int ws = g.x & 63;
            int hs = (g.x >> 6) & 63;
            int s  = hs * PLANE4 + ws;

            __half2 wab = *reinterpret_cast<__half2*>(&g.z);
            __half2 wcd = *reinterpret_cast<__half2*>(&g.w);
            __half2 waa = __half2half2(__low2half(wab));
            __half2 wbb = __half2half2(__high2half(wab));
            __half2 wcc = __half2half2(__low2half(wcd));
            __half2 wdd = __half2half2(__high2half(wcd));

            uint4 ul = sm[s];
            uint4 ur = sm[s + 1];
            uint4 dl = sm[s + PLANE4];
            uint4 dr = sm[s + PLANE4 + 1];

            float* o = obase + g.y;

            const unsigned* pul = &ul.x;
            const unsigned* pur = &ur.x;
            const unsigned* pdl = &dl.x;
            const unsigned* pdr = &dr.x;
            #pragma unroll
            for (int j = 0; j < 4; j++) {
                __half2 acc = __hmul2(*reinterpret_cast<const __half2*>(&pul[j]), waa);
                acc = __hfma2(*reinterpret_cast<const __half2*>(&pur[j]), wbb, acc);
                acc = __hfma2(*reinterpret_cast<const __half2*>(&pdl[j]), wcc, acc);
                acc = __hfma2(*reinterpret_cast<const __half2*>(&pdr[j]), wdd, acc);
                float2 f = __half22float2(acc);
                o[(2 * j)     * BINS] = f.x;
                o[(2 * j + 1) * BINS] = f.y;
            }
        }
    }
}

extern "C" void kernel_launch(void* const* d_in, const int* in_sizes, int n_in,
                              void* d_out, int out_size) {
    const float* features = (const float*)d_in[0];
    const float* rois     = (const float*)d_in[1];
    float* out            = (float*)d_out;

    cudaFuncSetAttribute(roialign_kernel,
                         cudaFuncAttributeMaxDynamicSharedMemorySize,
                         SMEM_BYTES);

    zero_cnt_kernel<<<1, 32>>>();
    build_list_kernel<<<N_ / 256, 256>>>(rois);
    {
        dim3 g((N_ * BINS + 255) / 256, B_);
        geom_kernel<<<g, 256>>>(rois);
    }
    {
        dim3 g((C_ / CH) * SLICES, B_);
        roialign_kernel<<<g, NTHREADS, SMEM_BYTES>>>(features, out);
    }
}